// round 1
// baseline (speedup 1.0000x reference)
#include <cuda_runtime.h>
#include <math.h>

#define Bq 32
#define Vq 2048
#define Pq 64
#define Aq 8
#define Fq 72          // P + A
#define NFq 128
#define NCOLS 200      // P + A + NF
#define VCHUNKS 8
#define VPC (Vq / VCHUNKS)   // 256
#define TWOF 144       // 2*F

// Scratch (device globals; no allocation allowed)
__device__ float g_vi [Bq * Vq * Pq];     // 16.8 MB
__device__ float g_agg[Bq * Vq * Aq];     //  2.1 MB
__device__ float g_T  [Bq * Vq * NFq];    // 33.5 MB
__device__ float g_M  [Bq * Aq * NFq];
__device__ float g_pmax[Bq * VCHUNKS * Aq * Fq];
__device__ float g_psum[Bq * VCHUNKS * Aq * Fq];

// ---------------------------------------------------------------------------
// Kernel A: fused GEMM  Y = X[BV,64] @ [W1 | W2 | Wout_top][64,200]
//   cols [0,64)   -> g_vi (= X@W1 + b1)
//   cols [64,72)  -> g_agg (= exp(-|X@W2 + b2|))
//   cols [72,200) -> g_T  (= X@Wout[0:64] + bout)
// One row per thread; W + bias staged in dynamic smem (52 KB).
// ---------------------------------------------------------------------------
__global__ void kA(const float* __restrict__ X,
                   const float* __restrict__ W1, const float* __restrict__ b1,
                   const float* __restrict__ W2, const float* __restrict__ b2,
                   const float* __restrict__ Wout, const float* __restrict__ bout) {
    extern __shared__ float sm[];
    float* Ws = sm;                  // [64][200]
    float* bs = sm + 64 * NCOLS;     // [200]
    const int tid = threadIdx.x;

    for (int i = tid; i < 64 * NCOLS; i += blockDim.x) {
        int k = i / NCOLS, j = i % NCOLS;
        float v;
        if (j < Pq)            v = W1[k * Pq + j];
        else if (j < Pq + Aq)  v = W2[k * Aq + (j - Pq)];
        else                   v = Wout[k * NFq + (j - Pq - Aq)];
        Ws[i] = v;
    }
    for (int j = tid; j < NCOLS; j += blockDim.x) {
        bs[j] = (j < Pq) ? b1[j] : (j < Pq + Aq) ? b2[j - Pq] : bout[j - Pq - Aq];
    }
    __syncthreads();

    const long row = (long)blockIdx.x * blockDim.x + tid;   // grid sized exactly

    float x[Pq];
    const float4* xr = (const float4*)(X + row * Pq);
#pragma unroll
    for (int i = 0; i < Pq / 4; i++) {
        float4 t = xr[i];
        x[4*i] = t.x; x[4*i+1] = t.y; x[4*i+2] = t.z; x[4*i+3] = t.w;
    }

    for (int c = 0; c < NCOLS / 4; c++) {
        const int j = 4 * c;
        float4 acc = *(const float4*)(bs + j);
#pragma unroll
        for (int k = 0; k < Pq; k++) {
            float4 w = *(const float4*)(Ws + k * NCOLS + j);
            acc.x = fmaf(x[k], w.x, acc.x);
            acc.y = fmaf(x[k], w.y, acc.y);
            acc.z = fmaf(x[k], w.z, acc.z);
            acc.w = fmaf(x[k], w.w, acc.w);
        }
        if (j < Pq) {
            *(float4*)(g_vi + row * Pq + j) = acc;
        } else if (j < Pq + Aq) {
            float4 r;
            r.x = expf(-fabsf(acc.x));
            r.y = expf(-fabsf(acc.y));
            r.z = expf(-fabsf(acc.z));
            r.w = expf(-fabsf(acc.w));
            *(float4*)(g_agg + row * Aq + (j - Pq)) = r;
        } else {
            *(float4*)(g_T + row * NFq + (j - Pq - Aq)) = acc;
        }
    }
}

// ---------------------------------------------------------------------------
// Kernel B1: partial max / sum over a V-chunk of prod[a,v,f] = agg[v,a]*feats[v,f]
// grid (VCHUNKS, B), 576 threads: thread -> (a = t%8, f = t/8)
// ---------------------------------------------------------------------------
__global__ void kB1() {
    const int b = blockIdx.y, ch = blockIdx.x;
    const int tid = threadIdx.x;           // 0..575
    const int a = tid % Aq;
    const int f = tid / Aq;                // 0..71

    __shared__ float sf[64][Fq + 1];       // feats tile, padded

    float vmax = -INFINITY, vsum = 0.f;
    const long base = (long)b * Vq + (long)ch * VPC;

    for (int t0 = 0; t0 < VPC; t0 += 64) {
        for (int i = tid; i < 64 * Pq; i += 576) {
            int r = i / Pq, c = i % Pq;
            sf[r][c] = g_vi[(base + t0 + r) * Pq + c];
        }
        for (int i = tid; i < 64 * Aq; i += 576) {
            int r = i / Aq, c = i % Aq;
            sf[r][Pq + c] = g_agg[(base + t0 + r) * Aq + c];
        }
        __syncthreads();
#pragma unroll 8
        for (int vv = 0; vv < 64; vv++) {
            float e = sf[vv][Pq + a];
            float p = e * sf[vv][f];
            vmax = fmaxf(vmax, p);
            vsum += p;
        }
        __syncthreads();
    }
    const long o = (((long)b * VCHUNKS + ch) * Aq + a) * Fq + f;
    g_pmax[o] = vmax;
    g_psum[o] = vsum;
}

// ---------------------------------------------------------------------------
// Kernel B2: combine partials -> collapsed[a, 2F]; then
//   M[b,a,n] = sum_g collapsed[a,g]*Wout[64 + a*144 + g, n] + Wout[1216+a, n]
// grid B, 576 threads
// ---------------------------------------------------------------------------
__global__ void kB2(const float* __restrict__ Wout) {
    const int b = blockIdx.x;
    const int tid = threadIdx.x;
    const int a = tid % Aq;
    const int f = tid / Aq;

    __shared__ float scol[Aq][TWOF];

    {
        float vmax = -INFINITY, vsum = 0.f;
        const long base = ((long)b * VCHUNKS) * Aq * Fq + a * Fq + f;
#pragma unroll
        for (int ch = 0; ch < VCHUNKS; ch++) {
            vmax = fmaxf(vmax, g_pmax[base + (long)ch * Aq * Fq]);
            vsum += g_psum[base + (long)ch * Aq * Fq];
        }
        scol[a][f]      = vmax;
        scol[a][Fq + f] = vsum * (1.0f / (float)Vq);
    }
    __syncthreads();

    for (int idx = tid; idx < Aq * NFq; idx += 576) {
        int aa = idx / NFq, n = idx % NFq;
        float acc = Wout[(Pq + Aq * TWOF + aa) * NFq + n];   // agg direct term (row 1216+aa)
#pragma unroll 16
        for (int g = 0; g < TWOF; g++) {
            acc = fmaf(scol[aa][g], Wout[(Pq + aa * TWOF + g) * NFq + n], acc);
        }
        g_M[(long)b * Aq * NFq + idx] = acc;
    }
}

// ---------------------------------------------------------------------------
// Kernel D: out[b,v,n] = tanh( T[b,v,n] + sum_a agg[b,v,a] * M[b,a,n] )
// grid B*V/64 blocks, 256 threads: thread -> (n = t%128, vh = t/128)
// ---------------------------------------------------------------------------
__global__ void kD(float* __restrict__ out) {
    const int blk = blockIdx.x;
    const int b   = blk / (Vq / 64);
    const int vt  = blk % (Vq / 64);
    const long v0 = (long)b * Vq + (long)vt * 64;
    const int tid = threadIdx.x;

    __shared__ float sM[Aq][NFq];
    __shared__ float sa[64][Aq];

    for (int i = tid; i < Aq * NFq; i += 256) sM[i / NFq][i % NFq] = g_M[(long)b * Aq * NFq + i];
    for (int i = tid; i < 64 * Aq;  i += 256) sa[i / Aq][i % Aq]  = g_agg[v0 * Aq + i];
    __syncthreads();

    const int n  = tid % NFq;
    const int vh = tid / NFq;     // 0 or 1

    float m[Aq];
#pragma unroll
    for (int a = 0; a < Aq; a++) m[a] = sM[a][n];

    for (int vv = vh; vv < 64; vv += 2) {
        float acc = g_T[(v0 + vv) * NFq + n];
#pragma unroll
        for (int a = 0; a < Aq; a++) acc = fmaf(sa[vv][a], m[a], acc);
        out[(v0 + vv) * NFq + n] = tanhf(acc);
    }
}

// ---------------------------------------------------------------------------
extern "C" void kernel_launch(void* const* d_in, const int* in_sizes, int n_in,
                              void* d_out, int out_size) {
    const float* X    = (const float*)d_in[0];
    const float* W1   = (const float*)d_in[1];
    const float* b1   = (const float*)d_in[2];
    const float* W2   = (const float*)d_in[3];
    const float* b2   = (const float*)d_in[4];
    const float* Wout = (const float*)d_in[5];
    const float* bout = (const float*)d_in[6];
    float* out = (float*)d_out;

    const int smemA = (64 * NCOLS + NCOLS) * sizeof(float);   // 52000 B
    cudaFuncSetAttribute(kA, cudaFuncAttributeMaxDynamicSharedMemorySize, smemA);

    kA<<<(Bq * Vq) / 128, 128, smemA>>>(X, W1, b1, W2, b2, Wout, bout);

    dim3 gB1(VCHUNKS, Bq);
    kB1<<<gB1, 576>>>();

    kB2<<<Bq, 576>>>(Wout);

    kD<<<(Bq * Vq) / 64, 256>>>(out);
}

// round 2
// speedup vs baseline: 1.4590x; 1.4590x over previous
#include <cuda_runtime.h>
#include <math.h>

#define Bq 32
#define Vq 2048
#define Pq 64
#define Aq 8
#define Fq 72          // P + A
#define NFq 128
#define TWOF 144       // 2*F
#define VCHUNKS 8
#define VPC (Vq / VCHUNKS)   // 256

// kA tiling
#define BM 64          // rows per block
#define BN 192         // vi(64) + T(128) columns
#define NTHR 192       // 8 row-groups x 24 col-groups
#define XT_STRIDE 68   // padded row length of transposed X tile

// Scratch (device globals; no allocation allowed)
__device__ float g_vi [Bq * Vq * Pq];     // 16.8 MB
__device__ float g_agg[Bq * Vq * Aq];     //  2.1 MB
__device__ float g_T  [Bq * Vq * NFq];    // 33.5 MB
__device__ float g_M  [Bq * Aq * NFq];
__device__ float g_pmax[Bq * VCHUNKS * Aq * Fq];
__device__ float g_psum[Bq * VCHUNKS * Aq * Fq];

typedef unsigned long long ull;

__device__ __forceinline__ void ffma2(ull& d, ull a, ull b) {
    asm("fma.rn.f32x2 %0, %1, %2, %0;" : "+l"(d) : "l"(a), "l"(b));
}
__device__ __forceinline__ ull pack2(float x) {
    ull r; asm("mov.b64 %0, {%1, %1};" : "=l"(r) : "f"(x)); return r;
}

// ---------------------------------------------------------------------------
// Kernel A: tiled GEMM  Y = X[BV,64] @ [W1 | Wout_top][64,192]  (f32x2 FMA)
//   cols [0,64)   -> g_vi (= X@W1 + b1)
//   cols [64,192) -> g_T  (= X@Wout[0:64] + bout)
// Epilogue (threads 0..63): agg = exp(-|X@W2 + b2|) from the smem X tile.
// ---------------------------------------------------------------------------
__global__ void __launch_bounds__(NTHR, 2)
kA(const float* __restrict__ X,
   const float* __restrict__ W1, const float* __restrict__ b1,
   const float* __restrict__ W2, const float* __restrict__ b2,
   const float* __restrict__ Wout, const float* __restrict__ bout) {
    extern __shared__ float sm[];
    float* Xt  = sm;                          // [64][XT_STRIDE]  transposed: Xt[k][row]
    float* Ws  = Xt + 64 * XT_STRIDE;         // [64][192]
    float* bs  = Ws + 64 * BN;                // [192]
    float* W2s = bs + BN;                     // [64][8]
    float* b2s = W2s + 64 * Aq;               // [8]

    const int tid  = threadIdx.x;
    const long row0 = (long)blockIdx.x * BM;

    // --- stage X tile (transposed) ---
    for (int i = tid; i < BM * 16; i += NTHR) {
        int r = i >> 4, kc = i & 15;
        float4 v = *(const float4*)(X + (row0 + r) * Pq + kc * 4);
        Xt[(kc * 4 + 0) * XT_STRIDE + r] = v.x;
        Xt[(kc * 4 + 1) * XT_STRIDE + r] = v.y;
        Xt[(kc * 4 + 2) * XT_STRIDE + r] = v.z;
        Xt[(kc * 4 + 3) * XT_STRIDE + r] = v.w;
    }
    // --- stage W (concat of W1 and Wout top 64 rows) ---
    for (int i = tid; i < 64 * BN; i += NTHR) {
        int k = i / BN, j = i % BN;
        Ws[i] = (j < Pq) ? W1[k * Pq + j] : Wout[k * NFq + (j - Pq)];
    }
    for (int j = tid; j < BN; j += NTHR)
        bs[j] = (j < Pq) ? b1[j] : bout[j - Pq];
    for (int i = tid; i < 64 * Aq; i += NTHR) W2s[i] = W2[i];
    if (tid < Aq) b2s[tid] = b2[tid];
    __syncthreads();

    const int tr = tid / 24;       // 0..7  -> rows tr*8 .. tr*8+7
    const int tc = tid % 24;       // 0..23 -> cols tc*8 .. tc*8+7

    ull acc[8][4];
#pragma unroll
    for (int r = 0; r < 8; r++)
#pragma unroll
        for (int p = 0; p < 4; p++) acc[r][p] = 0ull;

#pragma unroll 4
    for (int k = 0; k < Pq; k++) {
        const float* xr = Xt + k * XT_STRIDE + tr * 8;
        float4 xa = *(const float4*)(xr);
        float4 xb = *(const float4*)(xr + 4);
        const float* wr = Ws + k * BN + tc * 8;
        ulonglong2 w01 = *(const ulonglong2*)(wr);
        ulonglong2 w23 = *(const ulonglong2*)(wr + 4);
        ull w[4] = {w01.x, w01.y, w23.x, w23.y};
        ull xd[8] = {pack2(xa.x), pack2(xa.y), pack2(xa.z), pack2(xa.w),
                     pack2(xb.x), pack2(xb.y), pack2(xb.z), pack2(xb.w)};
#pragma unroll
        for (int r = 0; r < 8; r++)
#pragma unroll
            for (int p = 0; p < 4; p++) ffma2(acc[r][p], xd[r], w[p]);
    }

    // --- store main GEMM outputs ---
    const int j0 = tc * 8;
    float4 bA = *(const float4*)(bs + j0);
    float4 bB = *(const float4*)(bs + j0 + 4);
#pragma unroll
    for (int r = 0; r < 8; r++) {
        const long row = row0 + tr * 8 + r;
        union { ull u; float2 f; } c0, c1, c2, c3;
        c0.u = acc[r][0]; c1.u = acc[r][1]; c2.u = acc[r][2]; c3.u = acc[r][3];
        float4 oA = make_float4(c0.f.x + bA.x, c0.f.y + bA.y, c1.f.x + bA.z, c1.f.y + bA.w);
        float4 oB = make_float4(c2.f.x + bB.x, c2.f.y + bB.y, c3.f.x + bB.z, c3.f.y + bB.w);
        if (tc < 8) {
            float* dst = g_vi + row * Pq + j0;
            *(float4*)(dst)     = oA;
            *(float4*)(dst + 4) = oB;
        } else {
            float* dst = g_T + row * NFq + (j0 - Pq);
            *(float4*)(dst)     = oA;
            *(float4*)(dst + 4) = oB;
        }
    }

    // --- agg epilogue: threads 0..63 compute one row each from Xt ---
    if (tid < BM) {
        float a8[Aq];
#pragma unroll
        for (int a = 0; a < Aq; a++) a8[a] = b2s[a];
#pragma unroll 4
        for (int k = 0; k < Pq; k++) {
            float x = Xt[k * XT_STRIDE + tid];
#pragma unroll
            for (int a = 0; a < Aq; a++) a8[a] = fmaf(x, W2s[k * Aq + a], a8[a]);
        }
        float4 r0, r1;
        r0.x = expf(-fabsf(a8[0])); r0.y = expf(-fabsf(a8[1]));
        r0.z = expf(-fabsf(a8[2])); r0.w = expf(-fabsf(a8[3]));
        r1.x = expf(-fabsf(a8[4])); r1.y = expf(-fabsf(a8[5]));
        r1.z = expf(-fabsf(a8[6])); r1.w = expf(-fabsf(a8[7]));
        float* dst = g_agg + (row0 + tid) * Aq;
        *(float4*)(dst)     = r0;
        *(float4*)(dst + 4) = r1;
    }
}

// ---------------------------------------------------------------------------
// Kernel B1: partial max / sum over a V-chunk of prod[a,v,f] = agg[v,a]*feats[v,f]
// grid (VCHUNKS, B), 576 threads: thread -> (a = t%8, f = t/8)
// ---------------------------------------------------------------------------
__global__ void kB1() {
    const int b = blockIdx.y, ch = blockIdx.x;
    const int tid = threadIdx.x;           // 0..575
    const int a = tid % Aq;
    const int f = tid / Aq;                // 0..71

    __shared__ float sf[64][76];           // feats tile, padded stride 76

    float vmax = -INFINITY, vsum = 0.f;
    const long base = (long)b * Vq + (long)ch * VPC;

    for (int t0 = 0; t0 < VPC; t0 += 64) {
        for (int i = tid; i < 64 * 16; i += 576) {
            int r = i >> 4, c = i & 15;
            *(float4*)&sf[r][c * 4] = *(const float4*)(g_vi + (base + t0 + r) * Pq + c * 4);
        }
        for (int i = tid; i < 64 * 2; i += 576) {
            int r = i >> 1, c = i & 1;
            *(float4*)&sf[r][Pq + c * 4] = *(const float4*)(g_agg + (base + t0 + r) * Aq + c * 4);
        }
        __syncthreads();
#pragma unroll 8
        for (int vv = 0; vv < 64; vv++) {
            float e = sf[vv][Pq + a];
            float p = e * sf[vv][f];
            vmax = fmaxf(vmax, p);
            vsum += p;
        }
        __syncthreads();
    }
    const long o = (((long)b * VCHUNKS + ch) * Aq + a) * Fq + f;
    g_pmax[o] = vmax;
    g_psum[o] = vsum;
}

// ---------------------------------------------------------------------------
// Kernel B2: combine partials -> collapsed[a, 2F]; then
//   M[b,a,n] = sum_g collapsed[a,g]*Wout[64 + a*144 + g, n] + Wout[1216+a, n]
// grid B, 576 threads
// ---------------------------------------------------------------------------
__global__ void kB2(const float* __restrict__ Wout) {
    const int b = blockIdx.x;
    const int tid = threadIdx.x;
    const int a = tid % Aq;
    const int f = tid / Aq;

    __shared__ float scol[Aq][TWOF];

    {
        float vmax = -INFINITY, vsum = 0.f;
        const long base = ((long)b * VCHUNKS) * Aq * Fq + a * Fq + f;
#pragma unroll
        for (int ch = 0; ch < VCHUNKS; ch++) {
            vmax = fmaxf(vmax, g_pmax[base + (long)ch * Aq * Fq]);
            vsum += g_psum[base + (long)ch * Aq * Fq];
        }
        scol[a][f]      = vmax;
        scol[a][Fq + f] = vsum * (1.0f / (float)Vq);
    }
    __syncthreads();

    for (int idx = tid; idx < Aq * NFq; idx += 576) {
        int aa = idx / NFq, n = idx % NFq;
        float acc = Wout[(Pq + Aq * TWOF + aa) * NFq + n];   // agg direct term
#pragma unroll 16
        for (int g = 0; g < TWOF; g++) {
            acc = fmaf(scol[aa][g], Wout[(Pq + aa * TWOF + g) * NFq + n], acc);
        }
        g_M[(long)b * Aq * NFq + idx] = acc;
    }
}

// ---------------------------------------------------------------------------
// Kernel D: out[b,v,n] = tanh( T[b,v,n] + sum_a agg[b,v,a] * M[b,a,n] )
// grid B*V/64 blocks, 256 threads, float4 over n.
// ---------------------------------------------------------------------------
__global__ void __launch_bounds__(256)
kD(float* __restrict__ out) {
    const int blk = blockIdx.x;
    const int b   = blk / (Vq / 64);
    const int vt  = blk % (Vq / 64);
    const long v0 = (long)b * Vq + (long)vt * 64;
    const int tid = threadIdx.x;

    __shared__ float4 sM4[Aq][32];        // M[b,a,:] as 32 float4
    __shared__ float  sa[64][Aq];

    for (int i = tid; i < Aq * 32; i += 256)
        sM4[i >> 5][i & 31] = ((const float4*)(g_M + (long)b * Aq * NFq))[i];
    for (int i = tid; i < 64 * 2; i += 256)
        *(float4*)&sa[i >> 1][(i & 1) * 4] = ((const float4*)(g_agg + v0 * Aq))[i];
    __syncthreads();

    const int c4 = tid & 31;    // float4 column
    const int r0 = tid >> 5;    // 0..7

    float4 m[Aq];
#pragma unroll
    for (int a = 0; a < Aq; a++) m[a] = sM4[a][c4];

    for (int vv = r0; vv < 64; vv += 8) {
        float4 t = ((const float4*)(g_T + (v0 + vv) * NFq))[c4];
#pragma unroll
        for (int a = 0; a < Aq; a++) {
            float e = sa[vv][a];
            t.x = fmaf(e, m[a].x, t.x);
            t.y = fmaf(e, m[a].y, t.y);
            t.z = fmaf(e, m[a].z, t.z);
            t.w = fmaf(e, m[a].w, t.w);
        }
        float4 o;
        o.x = tanhf(t.x); o.y = tanhf(t.y); o.z = tanhf(t.z); o.w = tanhf(t.w);
        ((float4*)(out + (v0 + vv) * NFq))[c4] = o;
    }
}

// ---------------------------------------------------------------------------
extern "C" void kernel_launch(void* const* d_in, const int* in_sizes, int n_in,
                              void* d_out, int out_size) {
    const float* X    = (const float*)d_in[0];
    const float* W1   = (const float*)d_in[1];
    const float* b1   = (const float*)d_in[2];
    const float* W2   = (const float*)d_in[3];
    const float* b2   = (const float*)d_in[4];
    const float* Wout = (const float*)d_in[5];
    const float* bout = (const float*)d_in[6];
    float* out = (float*)d_out;

    const int smemA = (64 * XT_STRIDE + 64 * BN + BN + 64 * Aq + Aq) * sizeof(float);
    static int configured = 0;
    cudaFuncSetAttribute(kA, cudaFuncAttributeMaxDynamicSharedMemorySize, smemA);
    (void)configured;

    kA<<<(Bq * Vq) / BM, NTHR, smemA>>>(X, W1, b1, W2, b2, Wout, bout);

    dim3 gB1(VCHUNKS, Bq);
    kB1<<<gB1, 576>>>();

    kB2<<<Bq, 576>>>(Wout);

    kD<<<(Bq * Vq) / 64, 256>>>(out);
}